// round 5
// baseline (speedup 1.0000x reference)
#include <cuda_runtime.h>
#include <cuda_bf16.h>
#include <cstdint>
#include <math.h>

// Problem dims (fixed by the dataset)
#define T 4096
#define E 512

// -------------------- scratch (allocation-free: __device__ globals) ---------
__device__ float g_h1[(size_t)T * E];
__device__ float g_h2[(size_t)T * E];
__device__ float g_dot[(size_t)T * T];
__device__ float g_lg[(size_t)T * T];
__device__ float g_cmax[T];
__device__ float g_csum[T];

// ==================== tf32-split GEMM via mma.sync ==========================
// C[m,n] = sum_k A[m,k]*B[n,k] (+bias[n])
// f32 -> hi=tf32(v), lo=tf32(v-hi); product = hi*hi + hi*lo + lo*hi.
// hi/lo stored INTERLEAVED in smem (split once per element per CTA).
#define BM 128
#define BN 128
#define BK 16
#define ASTRU 40                    // u32 per smem row (16 hi/lo pairs + 8 pad)
#define TILE_F (BM * ASTRU)         // 5120 floats per matrix tile
#define STAGE_F (2 * TILE_F)        // A tile + B tile
#define GSMEM_BYTES (2 * STAGE_F * 4)  // 81920 B (2 stages)

__device__ __forceinline__ void tf32_split(float x, uint32_t& hb, uint32_t& lb) {
    asm("cvt.rna.tf32.f32 %0, %1;" : "=r"(hb) : "f"(x));
    float lf = x - __uint_as_float(hb);
    asm("cvt.rna.tf32.f32 %0, %1;" : "=r"(lb) : "f"(lf));
}

__device__ __forceinline__ void mma_16n8k8(float* c, const uint32_t* a,
                                           const uint32_t* b) {
    asm volatile(
        "mma.sync.aligned.m16n8k8.row.col.f32.tf32.tf32.f32 "
        "{%0,%1,%2,%3}, {%4,%5,%6,%7}, {%8,%9}, {%0,%1,%2,%3};"
        : "+f"(c[0]), "+f"(c[1]), "+f"(c[2]), "+f"(c[3])
        : "r"(a[0]), "r"(a[1]), "r"(a[2]), "r"(a[3]), "r"(b[0]), "r"(b[1]));
}

// split 8 raw floats -> 4 uint4 (hi,lo interleaved) at smem row lrow, k-offset half*8
__device__ __forceinline__ void split_sts(float* tile, int lrow, int half,
                                          const float4& v0, const float4& v1) {
    uint32_t h[8], l[8];
    tf32_split(v0.x, h[0], l[0]); tf32_split(v0.y, h[1], l[1]);
    tf32_split(v0.z, h[2], l[2]); tf32_split(v0.w, h[3], l[3]);
    tf32_split(v1.x, h[4], l[4]); tf32_split(v1.y, h[5], l[5]);
    tf32_split(v1.z, h[6], l[6]); tf32_split(v1.w, h[7], l[7]);
    uint4* dst = (uint4*)(tile + (size_t)lrow * ASTRU + half * 16);
    dst[0] = make_uint4(h[0], l[0], h[1], l[1]);
    dst[1] = make_uint4(h[2], l[2], h[3], l[3]);
    dst[2] = make_uint4(h[4], l[4], h[5], l[5]);
    dst[3] = make_uint4(h[6], l[6], h[7], l[7]);
}

__global__ __launch_bounds__(256) void gemm_tf32(
    const float* __restrict__ A0, const float* __restrict__ B0,
    const float* __restrict__ bias0, float* __restrict__ C0,
    const float* __restrict__ A1, const float* __restrict__ B1,
    const float* __restrict__ bias1, float* __restrict__ C1,
    int M, int N, int K) {
    extern __shared__ float sm[];

    const float* A = A0;
    const float* B = B0;
    const float* bias = bias0;
    float* C = C0;
    if (blockIdx.z == 1) { A = A1; B = B1; bias = bias1; C = C1; }

    const int tid = threadIdx.x;
    const int wid = tid >> 5;
    const int lane = tid & 31;
    const int m0 = blockIdx.y * BM;
    const int n0 = blockIdx.x * BN;

    // warp tile: 64 (M) x 32 (N); warp grid 2 x 4
    const int wm = (wid >> 2) * 64;
    const int wn = (wid & 3) * 32;
    const int qr = lane >> 2;
    const int qc = lane & 3;

    float acc[4][4][4];
#pragma unroll
    for (int i = 0; i < 4; i++)
#pragma unroll
        for (int j = 0; j < 4; j++)
#pragma unroll
            for (int v = 0; v < 4; v++) acc[i][j][v] = 0.f;

    const float* Abase = A + (size_t)m0 * K;
    const float* Bbase = B + (size_t)n0 * K;

    // tile-load mapping: each thread owns 8 consecutive k of one row
    const int lrow = tid >> 1;      // 0..127
    const int half = tid & 1;       // k-offset 0 or 8

    const int NC = K / BK;

    // ---- prologue: chunk 0 -> stage 0 --------------------------------------
    {
        const float* ap = Abase + (size_t)lrow * K + half * 8;
        const float* bp = Bbase + (size_t)lrow * K + half * 8;
        float4 a0 = *(const float4*)ap, a1 = *(const float4*)(ap + 4);
        float4 b0 = *(const float4*)bp, b1 = *(const float4*)(bp + 4);
        split_sts(sm, lrow, half, a0, a1);
        split_sts(sm + TILE_F, lrow, half, b0, b1);
    }
    __syncthreads();

    for (int c = 0; c < NC; c++) {
        const int s = c & 1;
        float4 a0, a1, b0, b1;
        const bool more = (c + 1 < NC);
        if (more) {
            const int k0 = (c + 1) * BK;
            const float* ap = Abase + (size_t)lrow * K + k0 + half * 8;
            const float* bp = Bbase + (size_t)lrow * K + k0 + half * 8;
            a0 = *(const float4*)ap; a1 = *(const float4*)(ap + 4);
            b0 = *(const float4*)bp; b1 = *(const float4*)(bp + 4);
        }

        // ---- MMA over stage s ---------------------------------------------
        const float* st = sm + s * STAGE_F;
        const float* stB = st + TILE_F;
#pragma unroll
        for (int ks = 0; ks < BK; ks += 8) {
            uint32_t ahi[4][4], alo[4][4];
#pragma unroll
            for (int mt = 0; mt < 4; mt++) {
                const int mr = wm + mt * 16;
                uint2 p0 = *(const uint2*)(st + (size_t)(mr + qr) * ASTRU + (ks + qc) * 2);
                uint2 p1 = *(const uint2*)(st + (size_t)(mr + qr + 8) * ASTRU + (ks + qc) * 2);
                uint2 p2 = *(const uint2*)(st + (size_t)(mr + qr) * ASTRU + (ks + qc + 4) * 2);
                uint2 p3 = *(const uint2*)(st + (size_t)(mr + qr + 8) * ASTRU + (ks + qc + 4) * 2);
                ahi[mt][0] = p0.x; alo[mt][0] = p0.y;
                ahi[mt][1] = p1.x; alo[mt][1] = p1.y;
                ahi[mt][2] = p2.x; alo[mt][2] = p2.y;
                ahi[mt][3] = p3.x; alo[mt][3] = p3.y;
            }
            uint32_t bhi[4][2], blo[4][2];
#pragma unroll
            for (int nt = 0; nt < 4; nt++) {
                const int nr = wn + nt * 8;
                uint2 q0 = *(const uint2*)(stB + (size_t)(nr + qr) * ASTRU + (ks + qc) * 2);
                uint2 q1 = *(const uint2*)(stB + (size_t)(nr + qr) * ASTRU + (ks + qc + 4) * 2);
                bhi[nt][0] = q0.x; blo[nt][0] = q0.y;
                bhi[nt][1] = q1.x; blo[nt][1] = q1.y;
            }
#pragma unroll
            for (int mt = 0; mt < 4; mt++)
#pragma unroll
                for (int nt = 0; nt < 4; nt++) {
                    mma_16n8k8(acc[mt][nt], ahi[mt], bhi[nt]);
                    mma_16n8k8(acc[mt][nt], ahi[mt], blo[nt]);
                    mma_16n8k8(acc[mt][nt], alo[mt], bhi[nt]);
                }
        }

        if (more) {
            float* stn = sm + ((c + 1) & 1) * STAGE_F;
            split_sts(stn, lrow, half, a0, a1);
            split_sts(stn + TILE_F, lrow, half, b0, b1);
        }
        __syncthreads();
    }

    // ---- epilogue ----------------------------------------------------------
#pragma unroll
    for (int mt = 0; mt < 4; mt++) {
#pragma unroll
        for (int nt = 0; nt < 4; nt++) {
            const int mrow = m0 + wm + mt * 16 + qr;
            const int ncol = n0 + wn + nt * 8 + qc * 2;
            float bx = 0.f, by = 0.f;
            if (bias) { bx = bias[ncol]; by = bias[ncol + 1]; }
            float2 v0 = make_float2(acc[mt][nt][0] + bx, acc[mt][nt][1] + by);
            float2 v1 = make_float2(acc[mt][nt][2] + bx, acc[mt][nt][3] + by);
            *(float2*)(C + (size_t)mrow * N + ncol) = v0;
            *(float2*)(C + (size_t)(mrow + 8) * N + ncol) = v1;
        }
    }
}

// -------------------- banded window sum + global add ------------------------
#define WR 128
#define WC 32
#define HALO 63

__global__ __launch_bounds__(256) void window_kernel(const float* __restrict__ dot,
                                                     const float* __restrict__ gatt,
                                                     float* __restrict__ lg) {
    __shared__ float s[WR + 2 * HALO][WC];

    const int r0 = blockIdx.y * WR;
    const int c0 = blockIdx.x * WC;
    const int tid = threadIdx.x;
    const int col = tid & 31;

    for (int rr = tid >> 5; rr < WR + 2 * HALO; rr += 8) {
        int gr = r0 - HALO + rr;
        float v = 0.f;
        if (gr >= 0 && gr < T) v = dot[(size_t)gr * T + c0 + col];
        s[rr][col] = v;
    }
    __syncthreads();

    const int strip = tid >> 5;
    const int i0 = strip * 16;

    float w0 = 0.f, w1 = 0.f, w2 = 0.f, w3 = 0.f;
#pragma unroll 8
    for (int t = 0; t < 124; t += 4) {
        w0 += s[i0 + t + 0][col];
        w1 += s[i0 + t + 1][col];
        w2 += s[i0 + t + 2][col];
        w3 += s[i0 + t + 3][col];
    }
    w0 += s[i0 + 124][col];
    w1 += s[i0 + 125][col];
    w2 += s[i0 + 126][col];
    float w = (w0 + w1) + (w2 + w3);

#pragma unroll
    for (int t = 0; t < 16; t++) {
        int gi = r0 + i0 + t;
        float val = w + gatt[(size_t)gi * T + c0 + col];
        lg[(size_t)gi * T + c0 + col] = val;
        if (t < 15) w += s[i0 + t + 127][col] - s[i0 + t][col];
    }
}

// -------------------- per-column max + sum(exp) -----------------------------
__global__ __launch_bounds__(256) void colreduce(const float* __restrict__ lg,
                                                 float* __restrict__ cmax,
                                                 float* __restrict__ csum) {
    const int c0 = blockIdx.x * 32;
    const int col = threadIdx.x & 31;
    const int seg = threadIdx.x >> 5;
    const int rbeg = seg * 512;

    __shared__ float sm[8][32];
    __shared__ float ss[8][32];

    float m0 = -1e30f, m1 = -1e30f, m2 = -1e30f, m3 = -1e30f;
    for (int r = rbeg; r < rbeg + 512; r += 4) {
        m0 = fmaxf(m0, lg[(size_t)(r + 0) * T + c0 + col]);
        m1 = fmaxf(m1, lg[(size_t)(r + 1) * T + c0 + col]);
        m2 = fmaxf(m2, lg[(size_t)(r + 2) * T + c0 + col]);
        m3 = fmaxf(m3, lg[(size_t)(r + 3) * T + c0 + col]);
    }
    sm[seg][col] = fmaxf(fmaxf(m0, m1), fmaxf(m2, m3));
    __syncthreads();
    if (seg == 0) {
        float mm = sm[0][col];
#pragma unroll
        for (int i = 1; i < 8; i++) mm = fmaxf(mm, sm[i][col]);
        sm[0][col] = mm;
    }
    __syncthreads();
    const float M = sm[0][col];

    float s0 = 0.f, s1 = 0.f, s2 = 0.f, s3 = 0.f;
    for (int r = rbeg; r < rbeg + 512; r += 4) {
        s0 += expf(lg[(size_t)(r + 0) * T + c0 + col] - M);
        s1 += expf(lg[(size_t)(r + 1) * T + c0 + col] - M);
        s2 += expf(lg[(size_t)(r + 2) * T + c0 + col] - M);
        s3 += expf(lg[(size_t)(r + 3) * T + c0 + col] - M);
    }
    ss[seg][col] = (s0 + s1) + (s2 + s3);
    __syncthreads();
    if (seg == 0) {
        float tt = 0.f;
#pragma unroll
        for (int i = 0; i < 8; i++) tt += ss[i][col];
        cmax[c0 + col] = M;
        csum[c0 + col] = tt;
    }
}

// -------------------- finalize: out = exp(lg - max_col) / sum_col -----------
__global__ __launch_bounds__(256) void finalize_kernel(const float* __restrict__ lg,
                                                       const float* __restrict__ cmax,
                                                       const float* __restrict__ csum,
                                                       float* __restrict__ out) {
    size_t i = (size_t)blockIdx.x * blockDim.x + threadIdx.x;
    size_t base = i * 4;
    int c = (int)(base & (T - 1));
    float4 v = *(const float4*)(lg + base);
    float4 M = *(const float4*)(cmax + c);
    float4 S = *(const float4*)(csum + c);
    float4 o;
    o.x = expf(v.x - M.x) / S.x;
    o.y = expf(v.y - M.y) / S.y;
    o.z = expf(v.z - M.z) / S.z;
    o.w = expf(v.w - M.w) / S.w;
    *(float4*)(out + base) = o;
}

// -------------------- launch ------------------------------------------------
extern "C" void kernel_launch(void* const* d_in, const int* in_sizes, int n_in,
                              void* d_out, int out_size) {
    const float* x1 = (const float*)d_in[0];   // (T, T)
    const float* x2 = (const float*)d_in[1];   // (T, T)
    const float* W1 = (const float*)d_in[2];   // (E, T)
    const float* b1 = (const float*)d_in[3];   // (E,)
    const float* W2 = (const float*)d_in[4];   // (E, T)
    const float* b2 = (const float*)d_in[5];   // (E,)
    const float* ga = (const float*)d_in[6];   // (T, T)
    float* out = (float*)d_out;

    float *h1, *h2, *dot, *lg, *cmax, *csum;
    cudaGetSymbolAddress((void**)&h1, g_h1);
    cudaGetSymbolAddress((void**)&h2, g_h2);
    cudaGetSymbolAddress((void**)&dot, g_dot);
    cudaGetSymbolAddress((void**)&lg, g_lg);
    cudaGetSymbolAddress((void**)&cmax, g_cmax);
    cudaGetSymbolAddress((void**)&csum, g_csum);

    cudaFuncSetAttribute(gemm_tf32, cudaFuncAttributeMaxDynamicSharedMemorySize,
                         GSMEM_BYTES);

    // batched: z=0 -> h1 = x1@W1^T+b1 ; z=1 -> h2 = x2@W2^T+b2  (M=T,N=E,K=T)
    gemm_tf32<<<dim3(E / BN, T / BM, 2), 256, GSMEM_BYTES>>>(
        x1, W1, b1, h1, x2, W2, b2, h2, T, E, T);
    // dot = h1 @ h2^T  (M=T, N=T, K=E)
    gemm_tf32<<<dim3(T / BN, T / BM, 1), 256, GSMEM_BYTES>>>(
        h1, h2, nullptr, dot, h1, h2, nullptr, dot, T, T, E);
    // lg = window(dot) + global_att
    window_kernel<<<dim3(T / WC, T / WR), 256>>>(dot, ga, lg);
    // column softmax stats
    colreduce<<<T / 32, 256>>>(lg, cmax, csum);
    // out = exp(lg - max)/sum
    finalize_kernel<<<((size_t)T * T / 4) / 256, 256>>>(lg, cmax, csum, out);
}

// round 6
// speedup vs baseline: 1.4940x; 1.4940x over previous
#include <cuda_runtime.h>
#include <cuda_bf16.h>
#include <cstdint>
#include <math.h>

// Problem dims (fixed by the dataset)
#define T 4096
#define E 512

// -------------------- scratch (allocation-free: __device__ globals) ---------
__device__ float g_h1[(size_t)T * E];
__device__ float g_h2[(size_t)T * E];
__device__ float g_u[(size_t)T * E];
__device__ float g_lg[(size_t)T * T];
__device__ float g_cmax[T];
__device__ float g_csum[T];

// ==================== tf32-split GEMM via mma.sync (R4-proven) ==============
// C[m,n] = sum_k A[m,k]*B[n,k] (+bias[n]) (+addmat[m,n])
#define BM 128
#define BN 128
#define BK 16
#define APAD 4
#define ASTR (BK + APAD)

__device__ __forceinline__ uint32_t smem_u32(const void* p) {
    uint32_t a;
    asm("{ .reg .u64 t; cvta.to.shared.u64 t, %1; cvt.u32.u64 %0, t; }"
        : "=r"(a) : "l"(p));
    return a;
}

__device__ __forceinline__ void cp_async16(uint32_t dst, const void* src) {
    asm volatile("cp.async.cg.shared.global [%0], [%1], 16;"
                 :: "r"(dst), "l"(src) : "memory");
}
#define CP_COMMIT() asm volatile("cp.async.commit_group;" ::: "memory")
#define CP_WAIT(N)  asm volatile("cp.async.wait_group %0;" :: "n"(N) : "memory")

__device__ __forceinline__ void tf32_split(float x, uint32_t& hb, uint32_t& lb) {
    asm("cvt.rna.tf32.f32 %0, %1;" : "=r"(hb) : "f"(x));
    float lf = x - __uint_as_float(hb);
    asm("cvt.rna.tf32.f32 %0, %1;" : "=r"(lb) : "f"(lf));
}

__device__ __forceinline__ void mma_16n8k8(float* c, const uint32_t* a,
                                           const uint32_t* b) {
    asm volatile(
        "mma.sync.aligned.m16n8k8.row.col.f32.tf32.tf32.f32 "
        "{%0,%1,%2,%3}, {%4,%5,%6,%7}, {%8,%9}, {%0,%1,%2,%3};"
        : "+f"(c[0]), "+f"(c[1]), "+f"(c[2]), "+f"(c[3])
        : "r"(a[0]), "r"(a[1]), "r"(a[2]), "r"(a[3]), "r"(b[0]), "r"(b[1]));
}

__global__ __launch_bounds__(256) void gemm_tf32(
    const float* __restrict__ A0, const float* __restrict__ B0,
    const float* __restrict__ bias0, float* __restrict__ C0,
    const float* __restrict__ A1, const float* __restrict__ B1,
    const float* __restrict__ bias1, float* __restrict__ C1,
    int M, int N, int K, const float* __restrict__ addmat) {
    __shared__ float As[2][BM][ASTR];
    __shared__ float Bs[2][BN][ASTR];

    const float* A = A0;
    const float* B = B0;
    const float* bias = bias0;
    float* C = C0;
    if (blockIdx.z == 1) { A = A1; B = B1; bias = bias1; C = C1; }

    const int tid = threadIdx.x;
    const int wid = tid >> 5;
    const int lane = tid & 31;
    const int m0 = blockIdx.y * BM;
    const int n0 = blockIdx.x * BN;

    // warp tile: 64 (M) x 32 (N); warp grid 2 x 4
    const int wm = (wid >> 2) * 64;
    const int wn = (wid & 3) * 32;
    const int qr = lane >> 2;
    const int qc = lane & 3;

    float acc[4][4][4];
#pragma unroll
    for (int i = 0; i < 4; i++)
#pragma unroll
        for (int j = 0; j < 4; j++)
#pragma unroll
            for (int v = 0; v < 4; v++) acc[i][j][v] = 0.f;

    const float* Abase = A + (size_t)m0 * K;
    const float* Bbase = B + (size_t)n0 * K;

    const int lrow = tid >> 2;
    const int lq = tid & 3;

    const int NC = K / BK;

    // ---- prologue ----------------------------------------------------------
    {
#pragma unroll
        for (int h = 0; h < 2; h++) {
            int row = lrow + h * 64;
            cp_async16(smem_u32(&As[0][row][lq * 4]),
                       Abase + (size_t)row * K + lq * 4);
            cp_async16(smem_u32(&Bs[0][row][lq * 4]),
                       Bbase + (size_t)row * K + lq * 4);
        }
        CP_COMMIT();
    }

    for (int c = 0; c < NC; c++) {
        const int s = c & 1;
        if (c + 1 < NC) {
            const int k0 = (c + 1) * BK;
            const int sn = (c + 1) & 1;
#pragma unroll
            for (int h = 0; h < 2; h++) {
                int row = lrow + h * 64;
                cp_async16(smem_u32(&As[sn][row][lq * 4]),
                           Abase + (size_t)row * K + k0 + lq * 4);
                cp_async16(smem_u32(&Bs[sn][row][lq * 4]),
                           Bbase + (size_t)row * K + k0 + lq * 4);
            }
            CP_COMMIT();
            CP_WAIT(1);
        } else {
            CP_WAIT(0);
        }
        __syncthreads();

#pragma unroll
        for (int ks = 0; ks < BK; ks += 8) {
            uint32_t ahi[4][4], alo[4][4];
#pragma unroll
            for (int mt = 0; mt < 4; mt++) {
                const int mr = wm + mt * 16;
                float r0 = As[s][mr + qr][ks + qc];
                float r1 = As[s][mr + qr + 8][ks + qc];
                float r2 = As[s][mr + qr][ks + qc + 4];
                float r3 = As[s][mr + qr + 8][ks + qc + 4];
                tf32_split(r0, ahi[mt][0], alo[mt][0]);
                tf32_split(r1, ahi[mt][1], alo[mt][1]);
                tf32_split(r2, ahi[mt][2], alo[mt][2]);
                tf32_split(r3, ahi[mt][3], alo[mt][3]);
            }
            uint32_t bhi[4][2], blo[4][2];
#pragma unroll
            for (int nt = 0; nt < 4; nt++) {
                const int nr = wn + nt * 8;
                float r0 = Bs[s][nr + qr][ks + qc];
                float r1 = Bs[s][nr + qr][ks + qc + 4];
                tf32_split(r0, bhi[nt][0], blo[nt][0]);
                tf32_split(r1, bhi[nt][1], blo[nt][1]);
            }
#pragma unroll
            for (int mt = 0; mt < 4; mt++)
#pragma unroll
                for (int nt = 0; nt < 4; nt++) {
                    mma_16n8k8(acc[mt][nt], ahi[mt], bhi[nt]);
                    mma_16n8k8(acc[mt][nt], ahi[mt], blo[nt]);
                    mma_16n8k8(acc[mt][nt], alo[mt], bhi[nt]);
                }
        }
        __syncthreads();
    }

    // ---- epilogue ----------------------------------------------------------
#pragma unroll
    for (int mt = 0; mt < 4; mt++) {
#pragma unroll
        for (int nt = 0; nt < 4; nt++) {
            const int mrow = m0 + wm + mt * 16 + qr;
            const int ncol = n0 + wn + nt * 8 + qc * 2;
            float bx = 0.f, by = 0.f;
            if (bias) { bx = bias[ncol]; by = bias[ncol + 1]; }
            float2 v0 = make_float2(acc[mt][nt][0] + bx, acc[mt][nt][1] + by);
            float2 v1 = make_float2(acc[mt][nt][2] + bx, acc[mt][nt][3] + by);
            if (addmat) {
                float2 g0 = *(const float2*)(addmat + (size_t)mrow * N + ncol);
                float2 g1 = *(const float2*)(addmat + (size_t)(mrow + 8) * N + ncol);
                v0.x += g0.x; v0.y += g0.y;
                v1.x += g1.x; v1.y += g1.y;
            }
            *(float2*)(C + (size_t)mrow * N + ncol) = v0;
            *(float2*)(C + (size_t)(mrow + 8) * N + ncol) = v1;
        }
    }
}

// -------------------- band row-sum of h1: u[i] = sum_{|k-i|<64} h1[k] -------
#define WR 128
#define WC 32
#define HALO 63

__global__ __launch_bounds__(256) void bandsum_kernel(const float* __restrict__ h,
                                                      float* __restrict__ u) {
    __shared__ float s[WR + 2 * HALO][WC];

    const int r0 = blockIdx.y * WR;
    const int c0 = blockIdx.x * WC;
    const int tid = threadIdx.x;
    const int col = tid & 31;

    for (int rr = tid >> 5; rr < WR + 2 * HALO; rr += 8) {
        int gr = r0 - HALO + rr;
        float v = 0.f;
        if (gr >= 0 && gr < T) v = h[(size_t)gr * E + c0 + col];
        s[rr][col] = v;
    }
    __syncthreads();

    const int strip = tid >> 5;
    const int i0 = strip * 16;

    float w0 = 0.f, w1 = 0.f, w2 = 0.f, w3 = 0.f;
#pragma unroll 8
    for (int t = 0; t < 124; t += 4) {
        w0 += s[i0 + t + 0][col];
        w1 += s[i0 + t + 1][col];
        w2 += s[i0 + t + 2][col];
        w3 += s[i0 + t + 3][col];
    }
    w0 += s[i0 + 124][col];
    w1 += s[i0 + 125][col];
    w2 += s[i0 + 126][col];
    float w = (w0 + w1) + (w2 + w3);

#pragma unroll
    for (int t = 0; t < 16; t++) {
        int gi = r0 + i0 + t;
        u[(size_t)gi * E + c0 + col] = w;
        if (t < 15) w += s[i0 + t + 127][col] - s[i0 + t][col];
    }
}

// -------------------- per-column max + sum(exp): 8 cols per CTA -------------
__global__ __launch_bounds__(256) void colreduce8(const float* __restrict__ lg,
                                                  float* __restrict__ cmax,
                                                  float* __restrict__ csum) {
    const int c0 = blockIdx.x * 8;
    const int col = threadIdx.x & 7;       // 0..7
    const int seg = threadIdx.x >> 3;      // 0..31
    const int rbeg = seg * 128;

    __shared__ float sm[32][9];
    __shared__ float ss[32][9];

    const float* base = lg + c0 + col;

    float m0 = -1e30f, m1 = -1e30f, m2 = -1e30f, m3 = -1e30f;
#pragma unroll 4
    for (int r = rbeg; r < rbeg + 128; r += 4) {
        m0 = fmaxf(m0, base[(size_t)(r + 0) * T]);
        m1 = fmaxf(m1, base[(size_t)(r + 1) * T]);
        m2 = fmaxf(m2, base[(size_t)(r + 2) * T]);
        m3 = fmaxf(m3, base[(size_t)(r + 3) * T]);
    }
    sm[seg][col] = fmaxf(fmaxf(m0, m1), fmaxf(m2, m3));
    __syncthreads();
    if (threadIdx.x < 8) {
        float mm = sm[0][threadIdx.x];
#pragma unroll
        for (int i = 1; i < 32; i++) mm = fmaxf(mm, sm[i][threadIdx.x]);
        sm[0][threadIdx.x] = mm;
    }
    __syncthreads();
    const float M = sm[0][col];

    float s0 = 0.f, s1 = 0.f, s2 = 0.f, s3 = 0.f;
#pragma unroll 4
    for (int r = rbeg; r < rbeg + 128; r += 4) {
        s0 += expf(base[(size_t)(r + 0) * T] - M);
        s1 += expf(base[(size_t)(r + 1) * T] - M);
        s2 += expf(base[(size_t)(r + 2) * T] - M);
        s3 += expf(base[(size_t)(r + 3) * T] - M);
    }
    ss[seg][col] = (s0 + s1) + (s2 + s3);
    __syncthreads();
    if (threadIdx.x < 8) {
        float tt = 0.f;
#pragma unroll
        for (int i = 0; i < 32; i++) tt += ss[i][threadIdx.x];
        cmax[c0 + threadIdx.x] = sm[0][threadIdx.x];
        csum[c0 + threadIdx.x] = tt;
    }
}

// -------------------- finalize: out = exp(lg - max_col) / sum_col -----------
__global__ __launch_bounds__(256) void finalize_kernel(const float* __restrict__ lg,
                                                       const float* __restrict__ cmax,
                                                       const float* __restrict__ csum,
                                                       float* __restrict__ out) {
    size_t i = (size_t)blockIdx.x * blockDim.x + threadIdx.x;
    size_t base = i * 4;
    int c = (int)(base & (T - 1));
    float4 v = *(const float4*)(lg + base);
    float4 M = *(const float4*)(cmax + c);
    float4 S = *(const float4*)(csum + c);
    float4 o;
    o.x = expf(v.x - M.x) / S.x;
    o.y = expf(v.y - M.y) / S.y;
    o.z = expf(v.z - M.z) / S.z;
    o.w = expf(v.w - M.w) / S.w;
    *(float4*)(out + base) = o;
}

// -------------------- launch ------------------------------------------------
extern "C" void kernel_launch(void* const* d_in, const int* in_sizes, int n_in,
                              void* d_out, int out_size) {
    const float* x1 = (const float*)d_in[0];   // (T, T)
    const float* x2 = (const float*)d_in[1];   // (T, T)
    const float* W1 = (const float*)d_in[2];   // (E, T)
    const float* b1 = (const float*)d_in[3];   // (E,)
    const float* W2 = (const float*)d_in[4];   // (E, T)
    const float* b2 = (const float*)d_in[5];   // (E,)
    const float* ga = (const float*)d_in[6];   // (T, T)
    float* out = (float*)d_out;

    float *h1, *h2, *u, *lg, *cmax, *csum;
    cudaGetSymbolAddress((void**)&h1, g_h1);
    cudaGetSymbolAddress((void**)&h2, g_h2);
    cudaGetSymbolAddress((void**)&u, g_u);
    cudaGetSymbolAddress((void**)&lg, g_lg);
    cudaGetSymbolAddress((void**)&cmax, g_cmax);
    cudaGetSymbolAddress((void**)&csum, g_csum);

    // batched: z=0 -> h1 = x1@W1^T+b1 ; z=1 -> h2 = x2@W2^T+b2  (M=T,N=E,K=T)
    gemm_tf32<<<dim3(E / BN, T / BM, 2), 256>>>(
        x1, W1, b1, h1, x2, W2, b2, h2, T, E, T, nullptr);
    // u = bandsum(h1)  (T x E)
    bandsum_kernel<<<dim3(E / WC, T / WR), 256>>>(h1, u);
    // lg = u @ h2^T + global_att  (M=T, N=T, K=E)
    gemm_tf32<<<dim3(T / BN, T / BM, 1), 256>>>(
        u, h2, nullptr, lg, u, h2, nullptr, lg, T, T, E, ga);
    // column softmax stats
    colreduce8<<<T / 8, 256>>>(lg, cmax, csum);
    // out = exp(lg - max)/sum
    finalize_kernel<<<((size_t)T * T / 4) / 256, 256>>>(lg, cmax, csum, out);
}

// round 7
// speedup vs baseline: 1.6144x; 1.0806x over previous
#include <cuda_runtime.h>
#include <cuda_bf16.h>
#include <cstdint>
#include <math.h>

// Problem dims (fixed by the dataset)
#define T 4096
#define E 512

// -------------------- scratch (allocation-free: __device__ globals) ---------
__device__ float g_h1[(size_t)T * E];
__device__ float g_h2[(size_t)T * E];
__device__ float g_u[(size_t)T * E];
__device__ float g_lg[(size_t)T * T];
__device__ float g_cmax[T];
__device__ float g_csum[T];

// ==================== tf32-split GEMM via mma.sync ==========================
// C[m,n] = sum_k A[m,k]*B[n,k] (+bias[n]) (+addmat[m,n])
#define BM 128
#define BN 128
#define BK 16
#define APAD 4
#define ASTR (BK + APAD)

__device__ __forceinline__ uint32_t smem_u32(const void* p) {
    uint32_t a;
    asm("{ .reg .u64 t; cvta.to.shared.u64 t, %1; cvt.u32.u64 %0, t; }"
        : "=r"(a) : "l"(p));
    return a;
}

__device__ __forceinline__ void cp_async16(uint32_t dst, const void* src) {
    asm volatile("cp.async.cg.shared.global [%0], [%1], 16;"
                 :: "r"(dst), "l"(src) : "memory");
}
#define CP_COMMIT() asm volatile("cp.async.commit_group;" ::: "memory")
#define CP_WAIT(N)  asm volatile("cp.async.wait_group %0;" :: "n"(N) : "memory")

__device__ __forceinline__ void tf32_split(float x, uint32_t& hb, uint32_t& lb) {
    asm("cvt.rna.tf32.f32 %0, %1;" : "=r"(hb) : "f"(x));
    float lf = x - __uint_as_float(hb);
    asm("cvt.rna.tf32.f32 %0, %1;" : "=r"(lb) : "f"(lf));
}

__device__ __forceinline__ void mma_16n8k8(float* c, const uint32_t* a,
                                           const uint32_t* b) {
    asm volatile(
        "mma.sync.aligned.m16n8k8.row.col.f32.tf32.tf32.f32 "
        "{%0,%1,%2,%3}, {%4,%5,%6,%7}, {%8,%9}, {%0,%1,%2,%3};"
        : "+f"(c[0]), "+f"(c[1]), "+f"(c[2]), "+f"(c[3])
        : "r"(a[0]), "r"(a[1]), "r"(a[2]), "r"(a[3]), "r"(b[0]), "r"(b[1]));
}

__global__ __launch_bounds__(256, 2) void gemm_tf32(
    const float* __restrict__ A0, const float* __restrict__ B0,
    const float* __restrict__ bias0, float* __restrict__ C0,
    const float* __restrict__ A1, const float* __restrict__ B1,
    const float* __restrict__ bias1, float* __restrict__ C1,
    int M, int N, int K, const float* __restrict__ addmat) {
    __shared__ float As[2][BM][ASTR];
    __shared__ float Bs[2][BN][ASTR];

    const float* A = A0;
    const float* B = B0;
    const float* bias = bias0;
    float* C = C0;
    if (blockIdx.z == 1) { A = A1; B = B1; bias = bias1; C = C1; }

    const int tid = threadIdx.x;
    const int wid = tid >> 5;
    const int lane = tid & 31;
    const int m0 = blockIdx.y * BM;
    const int n0 = blockIdx.x * BN;

    // warp tile: 64 (M) x 32 (N); warp grid 2 x 4
    const int wm = (wid >> 2) * 64;
    const int wn = (wid & 3) * 32;
    const int qr = lane >> 2;
    const int qc = lane & 3;

    float acc[4][4][4];
#pragma unroll
    for (int i = 0; i < 4; i++)
#pragma unroll
        for (int j = 0; j < 4; j++)
#pragma unroll
            for (int v = 0; v < 4; v++) acc[i][j][v] = 0.f;

    const float* Abase = A + (size_t)m0 * K;
    const float* Bbase = B + (size_t)n0 * K;

    const int lrow = tid >> 2;
    const int lq = tid & 3;

    const int NC = K / BK;

    // ---- prologue ----------------------------------------------------------
    {
#pragma unroll
        for (int h = 0; h < 2; h++) {
            int row = lrow + h * 64;
            cp_async16(smem_u32(&As[0][row][lq * 4]),
                       Abase + (size_t)row * K + lq * 4);
            cp_async16(smem_u32(&Bs[0][row][lq * 4]),
                       Bbase + (size_t)row * K + lq * 4);
        }
        CP_COMMIT();
    }

    for (int c = 0; c < NC; c++) {
        const int s = c & 1;
        if (c + 1 < NC) {
            const int k0 = (c + 1) * BK;
            const int sn = (c + 1) & 1;
#pragma unroll
            for (int h = 0; h < 2; h++) {
                int row = lrow + h * 64;
                cp_async16(smem_u32(&As[sn][row][lq * 4]),
                           Abase + (size_t)row * K + k0 + lq * 4);
                cp_async16(smem_u32(&Bs[sn][row][lq * 4]),
                           Bbase + (size_t)row * K + k0 + lq * 4);
            }
            CP_COMMIT();
            CP_WAIT(1);
        } else {
            CP_WAIT(0);
        }
        __syncthreads();

#pragma unroll
        for (int ks = 0; ks < BK; ks += 8) {
            uint32_t ahi[4][4], alo[4][4];
#pragma unroll
            for (int mt = 0; mt < 4; mt++) {
                const int mr = wm + mt * 16;
                float r0 = As[s][mr + qr][ks + qc];
                float r1 = As[s][mr + qr + 8][ks + qc];
                float r2 = As[s][mr + qr][ks + qc + 4];
                float r3 = As[s][mr + qr + 8][ks + qc + 4];
                tf32_split(r0, ahi[mt][0], alo[mt][0]);
                tf32_split(r1, ahi[mt][1], alo[mt][1]);
                tf32_split(r2, ahi[mt][2], alo[mt][2]);
                tf32_split(r3, ahi[mt][3], alo[mt][3]);
            }
            uint32_t bhi[4][2], blo[4][2];
#pragma unroll
            for (int nt = 0; nt < 4; nt++) {
                const int nr = wn + nt * 8;
                float r0 = Bs[s][nr + qr][ks + qc];
                float r1 = Bs[s][nr + qr][ks + qc + 4];
                tf32_split(r0, bhi[nt][0], blo[nt][0]);
                tf32_split(r1, bhi[nt][1], blo[nt][1]);
            }
            // p-outer: 16 independent MMAs between any accumulator reuse
#pragma unroll
            for (int mt = 0; mt < 4; mt++)
#pragma unroll
                for (int nt = 0; nt < 4; nt++)
                    mma_16n8k8(acc[mt][nt], ahi[mt], bhi[nt]);
#pragma unroll
            for (int mt = 0; mt < 4; mt++)
#pragma unroll
                for (int nt = 0; nt < 4; nt++)
                    mma_16n8k8(acc[mt][nt], ahi[mt], blo[nt]);
#pragma unroll
            for (int mt = 0; mt < 4; mt++)
#pragma unroll
                for (int nt = 0; nt < 4; nt++)
                    mma_16n8k8(acc[mt][nt], alo[mt], bhi[nt]);
        }
        __syncthreads();
    }

    // ---- epilogue ----------------------------------------------------------
#pragma unroll
    for (int mt = 0; mt < 4; mt++) {
#pragma unroll
        for (int nt = 0; nt < 4; nt++) {
            const int mrow = m0 + wm + mt * 16 + qr;
            const int ncol = n0 + wn + nt * 8 + qc * 2;
            float bx = 0.f, by = 0.f;
            if (bias) { bx = bias[ncol]; by = bias[ncol + 1]; }
            float2 v0 = make_float2(acc[mt][nt][0] + bx, acc[mt][nt][1] + by);
            float2 v1 = make_float2(acc[mt][nt][2] + bx, acc[mt][nt][3] + by);
            if (addmat) {
                float2 g0 = *(const float2*)(addmat + (size_t)mrow * N + ncol);
                float2 g1 = *(const float2*)(addmat + (size_t)(mrow + 8) * N + ncol);
                v0.x += g0.x; v0.y += g0.y;
                v1.x += g1.x; v1.y += g1.y;
            }
            *(float2*)(C + (size_t)mrow * N + ncol) = v0;
            *(float2*)(C + (size_t)(mrow + 8) * N + ncol) = v1;
        }
    }
}

// -------------------- band row-sum of h1: u[i] = sum_{|k-i|<64} h1[k] -------
#define WR 128
#define WC 32
#define HALO 63

__global__ __launch_bounds__(256) void bandsum_kernel(const float* __restrict__ h,
                                                      float* __restrict__ u) {
    __shared__ float s[WR + 2 * HALO][WC];

    const int r0 = blockIdx.y * WR;
    const int c0 = blockIdx.x * WC;
    const int tid = threadIdx.x;
    const int col = tid & 31;

    for (int rr = tid >> 5; rr < WR + 2 * HALO; rr += 8) {
        int gr = r0 - HALO + rr;
        float v = 0.f;
        if (gr >= 0 && gr < T) v = h[(size_t)gr * E + c0 + col];
        s[rr][col] = v;
    }
    __syncthreads();

    const int strip = tid >> 5;
    const int i0 = strip * 16;

    float w0 = 0.f, w1 = 0.f, w2 = 0.f, w3 = 0.f;
#pragma unroll 8
    for (int t = 0; t < 124; t += 4) {
        w0 += s[i0 + t + 0][col];
        w1 += s[i0 + t + 1][col];
        w2 += s[i0 + t + 2][col];
        w3 += s[i0 + t + 3][col];
    }
    w0 += s[i0 + 124][col];
    w1 += s[i0 + 125][col];
    w2 += s[i0 + 126][col];
    float w = (w0 + w1) + (w2 + w3);

#pragma unroll
    for (int t = 0; t < 16; t++) {
        int gi = r0 + i0 + t;
        u[(size_t)gi * E + c0 + col] = w;
        if (t < 15) w += s[i0 + t + 127][col] - s[i0 + t][col];
    }
}

// -------------------- per-column max + sum(exp): 8 cols per CTA -------------
__global__ __launch_bounds__(256) void colreduce8(const float* __restrict__ lg,
                                                  float* __restrict__ cmax,
                                                  float* __restrict__ csum) {
    const int c0 = blockIdx.x * 8;
    const int col = threadIdx.x & 7;       // 0..7
    const int seg = threadIdx.x >> 3;      // 0..31
    const int rbeg = seg * 128;

    __shared__ float sm[32][9];
    __shared__ float ss[32][9];

    const float* base = lg + c0 + col;

    float m0 = -1e30f, m1 = -1e30f, m2 = -1e30f, m3 = -1e30f;
#pragma unroll 4
    for (int r = rbeg; r < rbeg + 128; r += 4) {
        m0 = fmaxf(m0, base[(size_t)(r + 0) * T]);
        m1 = fmaxf(m1, base[(size_t)(r + 1) * T]);
        m2 = fmaxf(m2, base[(size_t)(r + 2) * T]);
        m3 = fmaxf(m3, base[(size_t)(r + 3) * T]);
    }
    sm[seg][col] = fmaxf(fmaxf(m0, m1), fmaxf(m2, m3));
    __syncthreads();
    if (threadIdx.x < 8) {
        float mm = sm[0][threadIdx.x];
#pragma unroll
        for (int i = 1; i < 32; i++) mm = fmaxf(mm, sm[i][threadIdx.x]);
        sm[0][threadIdx.x] = mm;
    }
    __syncthreads();
    const float M = sm[0][col];

    float s0 = 0.f, s1 = 0.f, s2 = 0.f, s3 = 0.f;
#pragma unroll 4
    for (int r = rbeg; r < rbeg + 128; r += 4) {
        s0 += expf(base[(size_t)(r + 0) * T] - M);
        s1 += expf(base[(size_t)(r + 1) * T] - M);
        s2 += expf(base[(size_t)(r + 2) * T] - M);
        s3 += expf(base[(size_t)(r + 3) * T] - M);
    }
    ss[seg][col] = (s0 + s1) + (s2 + s3);
    __syncthreads();
    if (threadIdx.x < 8) {
        float tt = 0.f;
#pragma unroll
        for (int i = 0; i < 32; i++) tt += ss[i][threadIdx.x];
        cmax[c0 + threadIdx.x] = sm[0][threadIdx.x];
        csum[c0 + threadIdx.x] = tt;
    }
}

// -------------------- finalize: out = exp(lg - max_col) / sum_col -----------
__global__ __launch_bounds__(256) void finalize_kernel(const float* __restrict__ lg,
                                                       const float* __restrict__ cmax,
                                                       const float* __restrict__ csum,
                                                       float* __restrict__ out) {
    size_t i = (size_t)blockIdx.x * blockDim.x + threadIdx.x;
    size_t base = i * 4;
    int c = (int)(base & (T - 1));
    float4 v = *(const float4*)(lg + base);
    float4 M = *(const float4*)(cmax + c);
    float4 S = *(const float4*)(csum + c);
    float4 o;
    o.x = expf(v.x - M.x) / S.x;
    o.y = expf(v.y - M.y) / S.y;
    o.z = expf(v.z - M.z) / S.z;
    o.w = expf(v.w - M.w) / S.w;
    *(float4*)(out + base) = o;
}

// -------------------- launch ------------------------------------------------
extern "C" void kernel_launch(void* const* d_in, const int* in_sizes, int n_in,
                              void* d_out, int out_size) {
    const float* x1 = (const float*)d_in[0];   // (T, T)
    const float* x2 = (const float*)d_in[1];   // (T, T)
    const float* W1 = (const float*)d_in[2];   // (E, T)
    const float* b1 = (const float*)d_in[3];   // (E,)
    const float* W2 = (const float*)d_in[4];   // (E, T)
    const float* b2 = (const float*)d_in[5];   // (E,)
    const float* ga = (const float*)d_in[6];   // (T, T)
    float* out = (float*)d_out;

    float *h1, *h2, *u, *lg, *cmax, *csum;
    cudaGetSymbolAddress((void**)&h1, g_h1);
    cudaGetSymbolAddress((void**)&h2, g_h2);
    cudaGetSymbolAddress((void**)&u, g_u);
    cudaGetSymbolAddress((void**)&lg, g_lg);
    cudaGetSymbolAddress((void**)&cmax, g_cmax);
    cudaGetSymbolAddress((void**)&csum, g_csum);

    // batched: z=0 -> h1 = x1@W1^T+b1 ; z=1 -> h2 = x2@W2^T+b2  (M=T,N=E,K=T)
    gemm_tf32<<<dim3(E / BN, T / BM, 2), 256>>>(
        x1, W1, b1, h1, x2, W2, b2, h2, T, E, T, nullptr);
    // u = bandsum(h1)  (T x E)
    bandsum_kernel<<<dim3(E / WC, T / WR), 256>>>(h1, u);
    // lg = u @ h2^T + global_att  (M=T, N=T, K=E)
    gemm_tf32<<<dim3(T / BN, T / BM, 1), 256>>>(
        u, h2, nullptr, lg, u, h2, nullptr, lg, T, T, E, ga);
    // column softmax stats
    colreduce8<<<T / 8, 256>>>(lg, cmax, csum);
    // out = exp(lg - max)/sum
    finalize_kernel<<<((size_t)T * T / 4) / 256, 256>>>(lg, cmax, csum, out);
}

// round 8
// speedup vs baseline: 1.8361x; 1.1373x over previous
#include <cuda_runtime.h>
#include <cuda_bf16.h>
#include <cstdint>
#include <math.h>

// Problem dims (fixed by the dataset)
#define T 4096
#define E 512

// -------------------- scratch (allocation-free: __device__ globals) ---------
__device__ float g_h1[(size_t)T * E];
__device__ float g_h2[(size_t)T * E];
__device__ float g_u[(size_t)T * E];
__device__ float g_lg[(size_t)T * T];
__device__ float g_cmax[T];
__device__ float g_csum[T];

// ==================== tf32-split GEMM via mma.sync ==========================
// C[m,n] = sum_k A[m,k]*B[n,k] (+bias[n]) (+addmat[m,n])
#define BM 128
#define BN 128
#define BK 16
#define APAD 4
#define ASTR (BK + APAD)
#define STAGE_F (2 * BM * ASTR)          // A tile + B tile floats per stage
#define NSTAGE 3
#define GSMEM_BYTES (NSTAGE * STAGE_F * 4)   // 61440 B

__device__ __forceinline__ uint32_t smem_u32(const void* p) {
    uint32_t a;
    asm("{ .reg .u64 t; cvta.to.shared.u64 t, %1; cvt.u32.u64 %0, t; }"
        : "=r"(a) : "l"(p));
    return a;
}

__device__ __forceinline__ void cp_async16(uint32_t dst, const void* src) {
    asm volatile("cp.async.cg.shared.global [%0], [%1], 16;"
                 :: "r"(dst), "l"(src) : "memory");
}
#define CP_COMMIT() asm volatile("cp.async.commit_group;" ::: "memory")
#define CP_WAIT(N)  asm volatile("cp.async.wait_group %0;" :: "n"(N) : "memory")

// hi = tf32_rna(x); lo = raw f32 residual (mma ignores low 13 mantissa bits)
__device__ __forceinline__ void tf32_split(float x, uint32_t& hb, uint32_t& lb) {
    asm("cvt.rna.tf32.f32 %0, %1;" : "=r"(hb) : "f"(x));
    lb = __float_as_uint(x - __uint_as_float(hb));
}

__device__ __forceinline__ void mma_16n8k8(float* c, const uint32_t* a,
                                           const uint32_t* b) {
    asm volatile(
        "mma.sync.aligned.m16n8k8.row.col.f32.tf32.tf32.f32 "
        "{%0,%1,%2,%3}, {%4,%5,%6,%7}, {%8,%9}, {%0,%1,%2,%3};"
        : "+f"(c[0]), "+f"(c[1]), "+f"(c[2]), "+f"(c[3])
        : "r"(a[0]), "r"(a[1]), "r"(a[2]), "r"(a[3]), "r"(b[0]), "r"(b[1]));
}

__global__ __launch_bounds__(256, 2) void gemm_tf32(
    const float* __restrict__ A0, const float* __restrict__ B0,
    const float* __restrict__ bias0, float* __restrict__ C0,
    const float* __restrict__ A1, const float* __restrict__ B1,
    const float* __restrict__ bias1, float* __restrict__ C1,
    int M, int N, int K, const float* __restrict__ addmat) {
    extern __shared__ float dsm[];

    const float* A = A0;
    const float* B = B0;
    const float* bias = bias0;
    float* C = C0;
    if (blockIdx.z == 1) { A = A1; B = B1; bias = bias1; C = C1; }

    const int tid = threadIdx.x;
    const int wid = tid >> 5;
    const int lane = tid & 31;
    const int m0 = blockIdx.y * BM;
    const int n0 = blockIdx.x * BN;

    // warp tile: 64 (M) x 32 (N); warp grid 2 x 4
    const int wm = (wid >> 2) * 64;
    const int wn = (wid & 3) * 32;
    const int qr = lane >> 2;
    const int qc = lane & 3;

    float acc[4][4][4];
#pragma unroll
    for (int i = 0; i < 4; i++)
#pragma unroll
        for (int j = 0; j < 4; j++)
#pragma unroll
            for (int v = 0; v < 4; v++) acc[i][j][v] = 0.f;

    const float* Abase = A + (size_t)m0 * K;
    const float* Bbase = B + (size_t)n0 * K;

    const int lrow = tid >> 2;
    const int lq = tid & 3;

    const int NC = K / BK;

    // issue cp.async for chunk c into stage c%NSTAGE
    auto issue = [&](int c) {
        const int k0 = c * BK;
        float* st = dsm + (c % NSTAGE) * STAGE_F;
        float* stB = st + BM * ASTR;
#pragma unroll
        for (int h = 0; h < 2; h++) {
            int row = lrow + h * 64;
            cp_async16(smem_u32(st + (size_t)row * ASTR + lq * 4),
                       Abase + (size_t)row * K + k0 + lq * 4);
            cp_async16(smem_u32(stB + (size_t)row * ASTR + lq * 4),
                       Bbase + (size_t)row * K + k0 + lq * 4);
        }
        CP_COMMIT();
    };

    // ---- prologue: chunks 0,1 in flight ------------------------------------
    issue(0);
    if (NC > 1) issue(1);

    for (int c = 0; c < NC; c++) {
        if (c < NC - 1) { CP_WAIT(1); } else { CP_WAIT(0); }
        __syncthreads();

        const float* st = dsm + (c % NSTAGE) * STAGE_F;
        const float* stB = st + BM * ASTR;

#pragma unroll
        for (int ks = 0; ks < BK; ks += 8) {
            uint32_t ahi[4][4], alo[4][4];
#pragma unroll
            for (int mt = 0; mt < 4; mt++) {
                const int mr = wm + mt * 16;
                float r0 = st[(size_t)(mr + qr) * ASTR + ks + qc];
                float r1 = st[(size_t)(mr + qr + 8) * ASTR + ks + qc];
                float r2 = st[(size_t)(mr + qr) * ASTR + ks + qc + 4];
                float r3 = st[(size_t)(mr + qr + 8) * ASTR + ks + qc + 4];
                tf32_split(r0, ahi[mt][0], alo[mt][0]);
                tf32_split(r1, ahi[mt][1], alo[mt][1]);
                tf32_split(r2, ahi[mt][2], alo[mt][2]);
                tf32_split(r3, ahi[mt][3], alo[mt][3]);
            }
            uint32_t bhi[4][2], blo[4][2];
#pragma unroll
            for (int nt = 0; nt < 4; nt++) {
                const int nr = wn + nt * 8;
                float r0 = stB[(size_t)(nr + qr) * ASTR + ks + qc];
                float r1 = stB[(size_t)(nr + qr) * ASTR + ks + qc + 4];
                tf32_split(r0, bhi[nt][0], blo[nt][0]);
                tf32_split(r1, bhi[nt][1], blo[nt][1]);
            }
            // p-outer: 16 independent MMAs between any accumulator reuse
#pragma unroll
            for (int mt = 0; mt < 4; mt++)
#pragma unroll
                for (int nt = 0; nt < 4; nt++)
                    mma_16n8k8(acc[mt][nt], ahi[mt], bhi[nt]);
#pragma unroll
            for (int mt = 0; mt < 4; mt++)
#pragma unroll
                for (int nt = 0; nt < 4; nt++)
                    mma_16n8k8(acc[mt][nt], ahi[mt], blo[nt]);
#pragma unroll
            for (int mt = 0; mt < 4; mt++)
#pragma unroll
                for (int nt = 0; nt < 4; nt++)
                    mma_16n8k8(acc[mt][nt], alo[mt], bhi[nt]);
        }

        if (c + 2 < NC) issue(c + 2);
    }

    // ---- epilogue ----------------------------------------------------------
#pragma unroll
    for (int mt = 0; mt < 4; mt++) {
#pragma unroll
        for (int nt = 0; nt < 4; nt++) {
            const int mrow = m0 + wm + mt * 16 + qr;
            const int ncol = n0 + wn + nt * 8 + qc * 2;
            float bx = 0.f, by = 0.f;
            if (bias) { bx = bias[ncol]; by = bias[ncol + 1]; }
            float2 v0 = make_float2(acc[mt][nt][0] + bx, acc[mt][nt][1] + by);
            float2 v1 = make_float2(acc[mt][nt][2] + bx, acc[mt][nt][3] + by);
            if (addmat) {
                float2 g0 = *(const float2*)(addmat + (size_t)mrow * N + ncol);
                float2 g1 = *(const float2*)(addmat + (size_t)(mrow + 8) * N + ncol);
                v0.x += g0.x; v0.y += g0.y;
                v1.x += g1.x; v1.y += g1.y;
            }
            *(float2*)(C + (size_t)mrow * N + ncol) = v0;
            *(float2*)(C + (size_t)(mrow + 8) * N + ncol) = v1;
        }
    }
}

// -------------------- band row-sum of h1: u[i] = sum_{|k-i|<64} h1[k] -------
#define WR 128
#define WC 32
#define HALO 63

__global__ __launch_bounds__(256) void bandsum_kernel(const float* __restrict__ h,
                                                      float* __restrict__ u) {
    __shared__ float s[WR + 2 * HALO][WC];

    const int r0 = blockIdx.y * WR;
    const int c0 = blockIdx.x * WC;
    const int tid = threadIdx.x;
    const int col = tid & 31;

    for (int rr = tid >> 5; rr < WR + 2 * HALO; rr += 8) {
        int gr = r0 - HALO + rr;
        float v = 0.f;
        if (gr >= 0 && gr < T) v = h[(size_t)gr * E + c0 + col];
        s[rr][col] = v;
    }
    __syncthreads();

    const int strip = tid >> 5;
    const int i0 = strip * 16;

    float w0 = 0.f, w1 = 0.f, w2 = 0.f, w3 = 0.f;
#pragma unroll 8
    for (int t = 0; t < 124; t += 4) {
        w0 += s[i0 + t + 0][col];
        w1 += s[i0 + t + 1][col];
        w2 += s[i0 + t + 2][col];
        w3 += s[i0 + t + 3][col];
    }
    w0 += s[i0 + 124][col];
    w1 += s[i0 + 125][col];
    w2 += s[i0 + 126][col];
    float w = (w0 + w1) + (w2 + w3);

#pragma unroll
    for (int t = 0; t < 16; t++) {
        int gi = r0 + i0 + t;
        u[(size_t)gi * E + c0 + col] = w;
        if (t < 15) w += s[i0 + t + 127][col] - s[i0 + t][col];
    }
}

// -------------------- per-column max + sum(exp): 8 cols per CTA -------------
__global__ __launch_bounds__(256) void colreduce8(const float* __restrict__ lg,
                                                  float* __restrict__ cmax,
                                                  float* __restrict__ csum) {
    const int c0 = blockIdx.x * 8;
    const int col = threadIdx.x & 7;       // 0..7
    const int seg = threadIdx.x >> 3;      // 0..31
    const int rbeg = seg * 128;

    __shared__ float sm[32][9];
    __shared__ float ss[32][9];

    const float* base = lg + c0 + col;

    float m0 = -1e30f, m1 = -1e30f, m2 = -1e30f, m3 = -1e30f;
#pragma unroll 4
    for (int r = rbeg; r < rbeg + 128; r += 4) {
        m0 = fmaxf(m0, base[(size_t)(r + 0) * T]);
        m1 = fmaxf(m1, base[(size_t)(r + 1) * T]);
        m2 = fmaxf(m2, base[(size_t)(r + 2) * T]);
        m3 = fmaxf(m3, base[(size_t)(r + 3) * T]);
    }
    sm[seg][col] = fmaxf(fmaxf(m0, m1), fmaxf(m2, m3));
    __syncthreads();
    if (threadIdx.x < 8) {
        float mm = sm[0][threadIdx.x];
#pragma unroll
        for (int i = 1; i < 32; i++) mm = fmaxf(mm, sm[i][threadIdx.x]);
        sm[0][threadIdx.x] = mm;
    }
    __syncthreads();
    const float M = sm[0][col];

    float s0 = 0.f, s1 = 0.f, s2 = 0.f, s3 = 0.f;
#pragma unroll 4
    for (int r = rbeg; r < rbeg + 128; r += 4) {
        s0 += expf(base[(size_t)(r + 0) * T] - M);
        s1 += expf(base[(size_t)(r + 1) * T] - M);
        s2 += expf(base[(size_t)(r + 2) * T] - M);
        s3 += expf(base[(size_t)(r + 3) * T] - M);
    }
    ss[seg][col] = (s0 + s1) + (s2 + s3);
    __syncthreads();
    if (threadIdx.x < 8) {
        float tt = 0.f;
#pragma unroll
        for (int i = 0; i < 32; i++) tt += ss[i][threadIdx.x];
        cmax[c0 + threadIdx.x] = sm[0][threadIdx.x];
        csum[c0 + threadIdx.x] = tt;
    }
}

// -------------------- finalize: out = exp(lg - max_col) / sum_col -----------
__global__ __launch_bounds__(256) void finalize_kernel(const float* __restrict__ lg,
                                                       const float* __restrict__ cmax,
                                                       const float* __restrict__ csum,
                                                       float* __restrict__ out) {
    size_t i = (size_t)blockIdx.x * blockDim.x + threadIdx.x;
    size_t base = i * 4;
    int c = (int)(base & (T - 1));
    float4 v = *(const float4*)(lg + base);
    float4 M = *(const float4*)(cmax + c);
    float4 S = *(const float4*)(csum + c);
    float4 o;
    o.x = expf(v.x - M.x) / S.x;
    o.y = expf(v.y - M.y) / S.y;
    o.z = expf(v.z - M.z) / S.z;
    o.w = expf(v.w - M.w) / S.w;
    *(float4*)(out + base) = o;
}

// -------------------- no-op: shifts ncu's captured launch onto gemm3 --------
__global__ void dummy_kernel() {}

// -------------------- launch ------------------------------------------------
extern "C" void kernel_launch(void* const* d_in, const int* in_sizes, int n_in,
                              void* d_out, int out_size) {
    const float* x1 = (const float*)d_in[0];   // (T, T)
    const float* x2 = (const float*)d_in[1];   // (T, T)
    const float* W1 = (const float*)d_in[2];   // (E, T)
    const float* b1 = (const float*)d_in[3];   // (E,)
    const float* W2 = (const float*)d_in[4];   // (E, T)
    const float* b2 = (const float*)d_in[5];   // (E,)
    const float* ga = (const float*)d_in[6];   // (T, T)
    float* out = (float*)d_out;

    float *h1, *h2, *u, *lg, *cmax, *csum;
    cudaGetSymbolAddress((void**)&h1, g_h1);
    cudaGetSymbolAddress((void**)&h2, g_h2);
    cudaGetSymbolAddress((void**)&u, g_u);
    cudaGetSymbolAddress((void**)&lg, g_lg);
    cudaGetSymbolAddress((void**)&cmax, g_cmax);
    cudaGetSymbolAddress((void**)&csum, g_csum);

    cudaFuncSetAttribute(gemm_tf32, cudaFuncAttributeMaxDynamicSharedMemorySize,
                         GSMEM_BYTES);

    // batched: z=0 -> h1 = x1@W1^T+b1 ; z=1 -> h2 = x2@W2^T+b2  (M=T,N=E,K=T)
    gemm_tf32<<<dim3(E / BN, T / BM, 2), 256, GSMEM_BYTES>>>(
        x1, W1, b1, h1, x2, W2, b2, h2, T, E, T, nullptr);
    // u = bandsum(h1)  (T x E)
    bandsum_kernel<<<dim3(E / WC, T / WR), 256>>>(h1, u);
    // lg = u @ h2^T + global_att  (M=T, N=T, K=E)
    gemm_tf32<<<dim3(T / BN, T / BM, 1), 256, GSMEM_BYTES>>>(
        u, h2, nullptr, lg, u, h2, nullptr, lg, T, T, E, ga);
    // column softmax stats
    colreduce8<<<T / 8, 256>>>(lg, cmax, csum);
    // out = exp(lg - max)/sum
    finalize_kernel<<<((size_t)T * T / 4) / 256, 256>>>(lg, cmax, csum, out);
    // no-op to align ncu's skip-count with gemm_tf32 (launch 8 = 6+2 = gemm3)
    dummy_kernel<<<1, 32>>>();
}

// round 9
// speedup vs baseline: 1.9887x; 1.0831x over previous
#include <cuda_runtime.h>
#include <cuda_bf16.h>
#include <cstdint>
#include <math.h>

// Problem dims (fixed by the dataset)
#define T 4096
#define E 512

// -------------------- scratch (allocation-free: __device__ globals) ---------
__device__ float g_h1[(size_t)T * E];
__device__ float g_h2[(size_t)T * E];
__device__ float g_u[(size_t)T * E];
__device__ float g_lg[(size_t)T * T];
__device__ float g_cmax[T];
__device__ float g_csum[T];

// ==================== hybrid tf32/bf16 split GEMM ===========================
// C[m,n] = sum_k A[m,k]*B[n,k] (+bias[n]) (+addmat[m,n])
// a = hi + lo (hi = tf32(a), lo = a - hi).
// hi*hi   -> tf32 m16n8k8 MMAs (11-bit operands)
// hi*lo + lo*hi -> bf16 m16n8k16 MMAs (8-bit operands suffice: err ~2^-21*ab)
#define BM 128
#define BN 128
#define BK 16
#define APAD 4
#define ASTR (BK + APAD)
#define STAGE_F (2 * BM * ASTR)          // A tile + B tile floats per stage
#define NSTAGE 3
#define GSMEM_BYTES (NSTAGE * STAGE_F * 4)   // 61440 B

__device__ __forceinline__ uint32_t smem_u32(const void* p) {
    uint32_t a;
    asm("{ .reg .u64 t; cvta.to.shared.u64 t, %1; cvt.u32.u64 %0, t; }"
        : "=r"(a) : "l"(p));
    return a;
}

__device__ __forceinline__ void cp_async16(uint32_t dst, const void* src) {
    asm volatile("cp.async.cg.shared.global [%0], [%1], 16;"
                 :: "r"(dst), "l"(src) : "memory");
}
#define CP_COMMIT() asm volatile("cp.async.commit_group;" ::: "memory")
#define CP_WAIT(N)  asm volatile("cp.async.wait_group %0;" :: "n"(N) : "memory")

__device__ __forceinline__ uint32_t cvt_tf32(float x) {
    uint32_t h;
    asm("cvt.rna.tf32.f32 %0, %1;" : "=r"(h) : "f"(x));
    return h;
}

// pack two floats to bf16x2: elem1 (upper bits) = e1, elem0 (lower) = e0
__device__ __forceinline__ uint32_t pack_bf16x2(float e1, float e0) {
    uint32_t d;
    asm("cvt.rn.bf16x2.f32 %0, %1, %2;" : "=r"(d) : "f"(e1), "f"(e0));
    return d;
}

__device__ __forceinline__ void mma_tf32_k8(float* c, const uint32_t* a,
                                            const uint32_t* b) {
    asm volatile(
        "mma.sync.aligned.m16n8k8.row.col.f32.tf32.tf32.f32 "
        "{%0,%1,%2,%3}, {%4,%5,%6,%7}, {%8,%9}, {%0,%1,%2,%3};"
        : "+f"(c[0]), "+f"(c[1]), "+f"(c[2]), "+f"(c[3])
        : "r"(a[0]), "r"(a[1]), "r"(a[2]), "r"(a[3]), "r"(b[0]), "r"(b[1]));
}

__device__ __forceinline__ void mma_bf16_k16(float* c, const uint32_t* a,
                                             const uint32_t* b) {
    asm volatile(
        "mma.sync.aligned.m16n8k16.row.col.f32.bf16.bf16.f32 "
        "{%0,%1,%2,%3}, {%4,%5,%6,%7}, {%8,%9}, {%0,%1,%2,%3};"
        : "+f"(c[0]), "+f"(c[1]), "+f"(c[2]), "+f"(c[3])
        : "r"(a[0]), "r"(a[1]), "r"(a[2]), "r"(a[3]), "r"(b[0]), "r"(b[1]));
}

// build hi-bf16x2 and lo-bf16x2 from a float2 (consecutive k)
__device__ __forceinline__ void split_bf(const float2 f, uint32_t& H, uint32_t& L) {
    H = pack_bf16x2(f.y, f.x);                         // hi ~ bf16(raw)
    float lx = f.x - __uint_as_float(cvt_tf32(f.x));
    float ly = f.y - __uint_as_float(cvt_tf32(f.y));
    L = pack_bf16x2(ly, lx);
}

__global__ __launch_bounds__(256, 2) void gemm_tf32(
    const float* __restrict__ A0, const float* __restrict__ B0,
    const float* __restrict__ bias0, float* __restrict__ C0,
    const float* __restrict__ A1, const float* __restrict__ B1,
    const float* __restrict__ bias1, float* __restrict__ C1,
    int M, int N, int K, const float* __restrict__ addmat) {
    extern __shared__ float dsm[];

    const float* A = A0;
    const float* B = B0;
    const float* bias = bias0;
    float* C = C0;
    if (blockIdx.z == 1) { A = A1; B = B1; bias = bias1; C = C1; }

    const int tid = threadIdx.x;
    const int wid = tid >> 5;
    const int lane = tid & 31;
    const int m0 = blockIdx.y * BM;
    const int n0 = blockIdx.x * BN;

    // warp tile: 64 (M) x 32 (N); warp grid 2 x 4
    const int wm = (wid >> 2) * 64;
    const int wn = (wid & 3) * 32;
    const int qr = lane >> 2;
    const int qc = lane & 3;

    float acc[4][4][4];
#pragma unroll
    for (int i = 0; i < 4; i++)
#pragma unroll
        for (int j = 0; j < 4; j++)
#pragma unroll
            for (int v = 0; v < 4; v++) acc[i][j][v] = 0.f;

    const float* Abase = A + (size_t)m0 * K;
    const float* Bbase = B + (size_t)n0 * K;

    const int lrow = tid >> 2;
    const int lq = tid & 3;

    const int NC = K / BK;

    auto issue = [&](int c) {
        const int k0 = c * BK;
        float* st = dsm + (c % NSTAGE) * STAGE_F;
        float* stB = st + BM * ASTR;
#pragma unroll
        for (int h = 0; h < 2; h++) {
            int row = lrow + h * 64;
            cp_async16(smem_u32(st + (size_t)row * ASTR + lq * 4),
                       Abase + (size_t)row * K + k0 + lq * 4);
            cp_async16(smem_u32(stB + (size_t)row * ASTR + lq * 4),
                       Bbase + (size_t)row * K + k0 + lq * 4);
        }
        CP_COMMIT();
    };

    issue(0);
    if (NC > 1) issue(1);

    for (int c = 0; c < NC; c++) {
        if (c < NC - 1) { CP_WAIT(1); } else { CP_WAIT(0); }
        __syncthreads();

        const float* st = dsm + (c % NSTAGE) * STAGE_F;
        const float* stB = st + BM * ASTR;

        // ---- tf32 hi*hi over two k8 slices --------------------------------
#pragma unroll
        for (int ks = 0; ks < BK; ks += 8) {
            uint32_t ahi[4][4];
#pragma unroll
            for (int mt = 0; mt < 4; mt++) {
                const int mr = wm + mt * 16;
                ahi[mt][0] = cvt_tf32(st[(size_t)(mr + qr) * ASTR + ks + qc]);
                ahi[mt][1] = cvt_tf32(st[(size_t)(mr + qr + 8) * ASTR + ks + qc]);
                ahi[mt][2] = cvt_tf32(st[(size_t)(mr + qr) * ASTR + ks + qc + 4]);
                ahi[mt][3] = cvt_tf32(st[(size_t)(mr + qr + 8) * ASTR + ks + qc + 4]);
            }
            uint32_t bhi[4][2];
#pragma unroll
            for (int nt = 0; nt < 4; nt++) {
                const int nr = wn + nt * 8;
                bhi[nt][0] = cvt_tf32(stB[(size_t)(nr + qr) * ASTR + ks + qc]);
                bhi[nt][1] = cvt_tf32(stB[(size_t)(nr + qr) * ASTR + ks + qc + 4]);
            }
#pragma unroll
            for (int mt = 0; mt < 4; mt++)
#pragma unroll
                for (int nt = 0; nt < 4; nt++)
                    mma_tf32_k8(acc[mt][nt], ahi[mt], bhi[nt]);
        }

        // ---- bf16 cross terms over one k16 slice --------------------------
        // B fragments (built once per chunk)
        uint32_t bH[4][2], bL[4][2];
#pragma unroll
        for (int nt = 0; nt < 4; nt++) {
            const int nr = wn + nt * 8;
            float2 g0 = *(const float2*)&stB[(size_t)(nr + qr) * ASTR + 2 * qc];
            float2 g1 = *(const float2*)&stB[(size_t)(nr + qr) * ASTR + 2 * qc + 8];
            split_bf(g0, bH[nt][0], bL[nt][0]);
            split_bf(g1, bH[nt][1], bL[nt][1]);
        }
#pragma unroll
        for (int mt = 0; mt < 4; mt++) {
            const int mr = wm + mt * 16;
            // A fragment regs: a0(qr,2qc) a1(qr+8,2qc) a2(qr,2qc+8) a3(qr+8,2qc+8)
            float2 f0 = *(const float2*)&st[(size_t)(mr + qr) * ASTR + 2 * qc];
            float2 f1 = *(const float2*)&st[(size_t)(mr + qr + 8) * ASTR + 2 * qc];
            float2 f2 = *(const float2*)&st[(size_t)(mr + qr) * ASTR + 2 * qc + 8];
            float2 f3 = *(const float2*)&st[(size_t)(mr + qr + 8) * ASTR + 2 * qc + 8];
            uint32_t aH[4], aL[4];
            split_bf(f0, aH[0], aL[0]);
            split_bf(f1, aH[1], aL[1]);
            split_bf(f2, aH[2], aL[2]);
            split_bf(f3, aH[3], aL[3]);
            // 4 independent MMAs per pass (distinct accumulators)
#pragma unroll
            for (int nt = 0; nt < 4; nt++)
                mma_bf16_k16(acc[mt][nt], aH, bL[nt]);
#pragma unroll
            for (int nt = 0; nt < 4; nt++)
                mma_bf16_k16(acc[mt][nt], aL, bH[nt]);
        }

        if (c + 2 < NC) issue(c + 2);
    }

    // ---- epilogue ----------------------------------------------------------
#pragma unroll
    for (int mt = 0; mt < 4; mt++) {
#pragma unroll
        for (int nt = 0; nt < 4; nt++) {
            const int mrow = m0 + wm + mt * 16 + qr;
            const int ncol = n0 + wn + nt * 8 + qc * 2;
            float bx = 0.f, by = 0.f;
            if (bias) { bx = bias[ncol]; by = bias[ncol + 1]; }
            float2 v0 = make_float2(acc[mt][nt][0] + bx, acc[mt][nt][1] + by);
            float2 v1 = make_float2(acc[mt][nt][2] + bx, acc[mt][nt][3] + by);
            if (addmat) {
                float2 g0 = *(const float2*)(addmat + (size_t)mrow * N + ncol);
                float2 g1 = *(const float2*)(addmat + (size_t)(mrow + 8) * N + ncol);
                v0.x += g0.x; v0.y += g0.y;
                v1.x += g1.x; v1.y += g1.y;
            }
            *(float2*)(C + (size_t)mrow * N + ncol) = v0;
            *(float2*)(C + (size_t)(mrow + 8) * N + ncol) = v1;
        }
    }
}

// -------------------- band row-sum of h1: u[i] = sum_{|k-i|<64} h1[k] -------
#define WR 128
#define WC 32
#define HALO 63

__global__ __launch_bounds__(256) void bandsum_kernel(const float* __restrict__ h,
                                                      float* __restrict__ u) {
    __shared__ float s[WR + 2 * HALO][WC];

    const int r0 = blockIdx.y * WR;
    const int c0 = blockIdx.x * WC;
    const int tid = threadIdx.x;
    const int col = tid & 31;

    for (int rr = tid >> 5; rr < WR + 2 * HALO; rr += 8) {
        int gr = r0 - HALO + rr;
        float v = 0.f;
        if (gr >= 0 && gr < T) v = h[(size_t)gr * E + c0 + col];
        s[rr][col] = v;
    }
    __syncthreads();

    const int strip = tid >> 5;
    const int i0 = strip * 16;

    float w0 = 0.f, w1 = 0.f, w2 = 0.f, w3 = 0.f;
#pragma unroll 8
    for (int t = 0; t < 124; t += 4) {
        w0 += s[i0 + t + 0][col];
        w1 += s[i0 + t + 1][col];
        w2 += s[i0 + t + 2][col];
        w3 += s[i0 + t + 3][col];
    }
    w0 += s[i0 + 124][col];
    w1 += s[i0 + 125][col];
    w2 += s[i0 + 126][col];
    float w = (w0 + w1) + (w2 + w3);

#pragma unroll
    for (int t = 0; t < 16; t++) {
        int gi = r0 + i0 + t;
        u[(size_t)gi * E + c0 + col] = w;
        if (t < 15) w += s[i0 + t + 127][col] - s[i0 + t][col];
    }
}

// -------------------- per-column max + sum(exp): 8 cols per CTA -------------
__global__ __launch_bounds__(256) void colreduce8(const float* __restrict__ lg,
                                                  float* __restrict__ cmax,
                                                  float* __restrict__ csum) {
    const int c0 = blockIdx.x * 8;
    const int col = threadIdx.x & 7;       // 0..7
    const int seg = threadIdx.x >> 3;      // 0..31
    const int rbeg = seg * 128;

    __shared__ float sm[32][9];
    __shared__ float ss[32][9];

    const float* base = lg + c0 + col;

    float m0 = -1e30f, m1 = -1e30f, m2 = -1e30f, m3 = -1e30f;
#pragma unroll 4
    for (int r = rbeg; r < rbeg + 128; r += 4) {
        m0 = fmaxf(m0, base[(size_t)(r + 0) * T]);
        m1 = fmaxf(m1, base[(size_t)(r + 1) * T]);
        m2 = fmaxf(m2, base[(size_t)(r + 2) * T]);
        m3 = fmaxf(m3, base[(size_t)(r + 3) * T]);
    }
    sm[seg][col] = fmaxf(fmaxf(m0, m1), fmaxf(m2, m3));
    __syncthreads();
    if (threadIdx.x < 8) {
        float mm = sm[0][threadIdx.x];
#pragma unroll
        for (int i = 1; i < 32; i++) mm = fmaxf(mm, sm[i][threadIdx.x]);
        sm[0][threadIdx.x] = mm;
    }
    __syncthreads();
    const float M = sm[0][col];

    float s0 = 0.f, s1 = 0.f, s2 = 0.f, s3 = 0.f;
#pragma unroll 4
    for (int r = rbeg; r < rbeg + 128; r += 4) {
        s0 += expf(base[(size_t)(r + 0) * T] - M);
        s1 += expf(base[(size_t)(r + 1) * T] - M);
        s2 += expf(base[(size_t)(r + 2) * T] - M);
        s3 += expf(base[(size_t)(r + 3) * T] - M);
    }
    ss[seg][col] = (s0 + s1) + (s2 + s3);
    __syncthreads();
    if (threadIdx.x < 8) {
        float tt = 0.f;
#pragma unroll
        for (int i = 0; i < 32; i++) tt += ss[i][threadIdx.x];
        cmax[c0 + threadIdx.x] = sm[0][threadIdx.x];
        csum[c0 + threadIdx.x] = tt;
    }
}

// -------------------- finalize: out = exp(lg - max_col) / sum_col -----------
__global__ __launch_bounds__(256) void finalize_kernel(const float* __restrict__ lg,
                                                       const float* __restrict__ cmax,
                                                       const float* __restrict__ csum,
                                                       float* __restrict__ out) {
    size_t i = (size_t)blockIdx.x * blockDim.x + threadIdx.x;
    size_t base = i * 4;
    int c = (int)(base & (T - 1));
    float4 v = *(const float4*)(lg + base);
    float4 M = *(const float4*)(cmax + c);
    float4 S = *(const float4*)(csum + c);
    float4 o;
    o.x = expf(v.x - M.x) / S.x;
    o.y = expf(v.y - M.y) / S.y;
    o.z = expf(v.z - M.z) / S.z;
    o.w = expf(v.w - M.w) / S.w;
    *(float4*)(out + base) = o;
}

// -------------------- launch ------------------------------------------------
extern "C" void kernel_launch(void* const* d_in, const int* in_sizes, int n_in,
                              void* d_out, int out_size) {
    const float* x1 = (const float*)d_in[0];   // (T, T)
    const float* x2 = (const float*)d_in[1];   // (T, T)
    const float* W1 = (const float*)d_in[2];   // (E, T)
    const float* b1 = (const float*)d_in[3];   // (E,)
    const float* W2 = (const float*)d_in[4];   // (E, T)
    const float* b2 = (const float*)d_in[5];   // (E,)
    const float* ga = (const float*)d_in[6];   // (T, T)
    float* out = (float*)d_out;

    float *h1, *h2, *u, *lg, *cmax, *csum;
    cudaGetSymbolAddress((void**)&h1, g_h1);
    cudaGetSymbolAddress((void**)&h2, g_h2);
    cudaGetSymbolAddress((void**)&u, g_u);
    cudaGetSymbolAddress((void**)&lg, g_lg);
    cudaGetSymbolAddress((void**)&cmax, g_cmax);
    cudaGetSymbolAddress((void**)&csum, g_csum);

    cudaFuncSetAttribute(gemm_tf32, cudaFuncAttributeMaxDynamicSharedMemorySize,
                         GSMEM_BYTES);

    // batched: z=0 -> h1 = x1@W1^T+b1 ; z=1 -> h2 = x2@W2^T+b2  (M=T,N=E,K=T)
    gemm_tf32<<<dim3(E / BN, T / BM, 2), 256, GSMEM_BYTES>>>(
        x1, W1, b1, h1, x2, W2, b2, h2, T, E, T, nullptr);
    // u = bandsum(h1)  (T x E)
    bandsum_kernel<<<dim3(E / WC, T / WR), 256>>>(h1, u);
    // lg = u @ h2^T + global_att  (M=T, N=T, K=E)
    gemm_tf32<<<dim3(T / BN, T / BM, 1), 256, GSMEM_BYTES>>>(
        u, h2, nullptr, lg, u, h2, nullptr, lg, T, T, E, ga);
    // column softmax stats
    colreduce8<<<T / 8, 256>>>(lg, cmax, csum);
    // out = exp(lg - max)/sum
    finalize_kernel<<<((size_t)T * T / 4) / 256, 256>>>(lg, cmax, csum, out);
}